// round 12
// baseline (speedup 1.0000x reference)
#include <cuda_runtime.h>
#include <cuda_bf16.h>

// ---------------------------------------------------------------------------
// CNN_22952305230196: conv(3->4,3x3,SAME)+relu+avgpool2 -> conv(4->16)+relu+
// avgpool2 -> NetVLAD (K=4, D=16) -> intra L2 norm -> global L2 norm -> 64x7.
// N=32, input 512x512. Output (32,7) float32.
//
// R10 ncu (conv1): alu=40.1% ~ fma=39.8% -> boundary SELs/packs/address math
// co-bottleneck with math. This round: (a) conv2 reads a ZERO-PADDED g_h1
// (258x264 per (n,c), interior at (+1,+2)) -> no bounds logic at all, affine
// addresses; (b) conv1 takes a y-interior fast path (warp-uniform branch).
// Packed f32x2 math + halving butterfly reduction kept from R10.
// ---------------------------------------------------------------------------

#define NIMG 32
#define H1H 258
#define H1W 264
#define H1CH (H1H * H1W)   // 68112 floats per (n,c)

typedef unsigned long long u64t;

#define FMA2(acc, a, b) \
    asm("fma.rn.f32x2 %0, %1, %2, %0;" : "+l"(acc) : "l"(a), "l"(b))
#define ADD2(acc, a) \
    asm("add.rn.f32x2 %0, %0, %1;" : "+l"(acc) : "l"(a))
#define MUL2(d, a, b) \
    asm("mul.rn.f32x2 %0, %1, %2;" : "=l"(d) : "l"(a), "l"(b))
#define PACK2(d, lo, hi) \
    asm("mov.b64 %0, {%1, %2};" : "=l"(d) : "f"(lo), "f"(hi))
#define UNPACK2(lo, hi, s) \
    asm("mov.b64 {%0, %1}, %2;" : "=f"(lo), "=f"(hi) : "l"(s))

// scratch (allowed: __device__ globals, no allocation)
__device__ float g_h1p[NIMG * 4 * H1CH];        // 34.9 MB, zero-padded
__device__ u64t  g_vpart[NIMG * 16 * 34];       // [n][chunk] 34 packed pairs

// ---------------------------------------------------------------------------
// Kernel 0: zero the padded border of g_h1p (rows 0,257 full; cols 1,258 for
// rows 1..256). 128 blocks (one per (n,c)) x 256 threads.
// ---------------------------------------------------------------------------
__global__ void __launch_bounds__(256) k_zero()
{
    float* p = g_h1p + (size_t)blockIdx.x * H1CH;
    for (int i = threadIdx.x; i < 2 * H1W; i += 256) {
        int col = i % H1W;
        int row = (i < H1W) ? 0 : (H1H - 1);
        p[row * H1W + col] = 0.0f;
    }
    for (int i = threadIdx.x; i < 2 * 256; i += 256) {
        int row = 1 + (i & 255);
        int col = (i < 256) ? 1 : 258;
        p[row * H1W + col] = 0.0f;
    }
}

// ---------------------------------------------------------------------------
// Kernel 1: conv1 (3->4, 3x3 SAME) + relu + 2x2 avgpool. One thread = TWO
// adjacent pooled pixels; channel-outer. Warp-uniform y-interior fast path
// (py in [1,254]) avoids all yok SELs and keeps addresses affine.
// Writes padded g_h1p interior. grid: 4096 blocks x 256 threads.
// ---------------------------------------------------------------------------
__global__ void __launch_bounds__(256, 2) k_conv1(
    const float* __restrict__ x, const float* __restrict__ w,
    const float* __restrict__ b)
{
    __shared__ float2 s_wd[108];  // (4,3,3,3) duplicated
    __shared__ float2 s_bd[4];
    int t = threadIdx.x;
    if (t < 108) { float v = w[t]; s_wd[t] = make_float2(v, v); }
    if (t < 4)   { float v = b[t]; s_bd[t] = make_float2(v, v); }
    __syncthreads();

    int idx = blockIdx.x * 256 + t;
    int qx = idx & 127;           // pixel-pair index: pixels 2qx, 2qx+1
    int py = (idx >> 7) & 255;
    int n  = idx >> 15;

    int y0 = 2 * py - 1;          // top input row (may be -1)
    int xb = 4 * qx;              // 16B-aligned input column of the float4
    bool left  = (qx > 0);
    bool right = (qx < 127);
    bool yint  = (py > 0) && (py < 255);   // warp-uniform

    // acc[oc][0]=A-top, [1]=A-bot, [2]=B-top, [3]=B-bot (packed pooled pairs)
    u64t acc[4][4];
#pragma unroll
    for (int oc = 0; oc < 4; oc++) {
        u64t bias = *(const u64t*)&s_bd[oc];
        acc[oc][0] = bias; acc[oc][1] = bias;
        acc[oc][2] = bias; acc[oc][3] = bias;
    }

#pragma unroll
    for (int c = 0; c < 3; c++) {
        // pairs p[j] = (in[xb-1+j], in[xb+j]), j=0..4; A uses 0..2, B 2..4
        u64t prc[4][5];
        const float* xp = x + ((size_t)(n * 3 + c) << 18);  // *512*512
        if (yint) {
            const float* rp0 = xp + (size_t)y0 * 512;
#pragma unroll
            for (int r = 0; r < 4; r++) {
                const float* rp = rp0 + r * 512;
                float4 f = __ldg((const float4*)(rp + xb));
                float vm1 = left  ? __ldg(rp + xb - 1) : 0.0f;
                float vp4 = right ? __ldg(rp + xb + 4) : 0.0f;
                PACK2(prc[r][0], vm1, f.x);
                PACK2(prc[r][1], f.x, f.y);
                PACK2(prc[r][2], f.y, f.z);
                PACK2(prc[r][3], f.z, f.w);
                PACK2(prc[r][4], f.w, vp4);
            }
        } else {
#pragma unroll
            for (int r = 0; r < 4; r++) {
                int iy = y0 + r;
                bool yok = (unsigned)iy < 512u;
                const float* rp = xp + iy * 512;
                float4 f = yok ? __ldg((const float4*)(rp + xb))
                               : make_float4(0.f, 0.f, 0.f, 0.f);
                float vm1 = (yok && left)  ? __ldg(rp + xb - 1) : 0.0f;
                float vp4 = (yok && right) ? __ldg(rp + xb + 4) : 0.0f;
                PACK2(prc[r][0], vm1, f.x);
                PACK2(prc[r][1], f.x, f.y);
                PACK2(prc[r][2], f.y, f.z);
                PACK2(prc[r][3], f.z, f.w);
                PACK2(prc[r][4], f.w, vp4);
            }
        }
#pragma unroll
        for (int oc = 0; oc < 4; oc++)
#pragma unroll
            for (int ky = 0; ky < 3; ky++)
#pragma unroll
                for (int kx = 0; kx < 3; kx++) {
                    u64t wd = *(const u64t*)&s_wd[((oc * 3 + c) * 3 + ky) * 3 + kx];
                    FMA2(acc[oc][0], prc[ky    ][kx    ], wd);
                    FMA2(acc[oc][1], prc[ky + 1][kx    ], wd);
                    FMA2(acc[oc][2], prc[ky    ][kx + 2], wd);
                    FMA2(acc[oc][3], prc[ky + 1][kx + 2], wd);
                }
    }

#pragma unroll
    for (int oc = 0; oc < 4; oc++) {
        float a00, a01, a10, a11, b00, b01, b10, b11;
        UNPACK2(a00, a01, acc[oc][0]);
        UNPACK2(a10, a11, acc[oc][1]);
        UNPACK2(b00, b01, acc[oc][2]);
        UNPACK2(b10, b11, acc[oc][3]);
        float rA = 0.25f * (fmaxf(a00, 0.f) + fmaxf(a01, 0.f) +
                            fmaxf(a10, 0.f) + fmaxf(a11, 0.f));
        float rB = 0.25f * (fmaxf(b00, 0.f) + fmaxf(b01, 0.f) +
                            fmaxf(b10, 0.f) + fmaxf(b11, 0.f));
        // padded interior: row py+1, col 2+2qx (8B aligned)
        *(float2*)&g_h1p[(size_t)(n * 4 + oc) * H1CH + (py + 1) * H1W + 2 + 2 * qx] =
            make_float2(rA, rB);
    }
}

// ---------------------------------------------------------------------------
// Kernel 2: conv2 (4->16) + relu + avgpool2 FUSED with NetVLAD soft-assign.
// Reads zero-padded g_h1p: NO bounds logic, affine addresses. 4 px/thread,
// two 8-oc sweeps, per-pixel recursive-halving butterfly (lane l ends with
// warp-sum of value l). grid: 512 blocks x 256 threads; n = blockIdx.x >> 4.
// ---------------------------------------------------------------------------
__global__ void __launch_bounds__(256, 2) k_conv2_vlad(
    const float* __restrict__ w, const float* __restrict__ b,
    const float* __restrict__ aw, const float* __restrict__ ab)
{
    __shared__ float2 s_wd[576];  // (16,4,3,3) duplicated
    __shared__ float2 s_bd[16];
    __shared__ float  s_aw[64];   // assign_w (K=4, D=16)
    __shared__ float  s_ab[4];
    __shared__ u64t   s_red[8][34];
    int t = threadIdx.x;
    for (int i = t; i < 576; i += 256) { float v = w[i]; s_wd[i] = make_float2(v, v); }
    if (t < 16) { float v = b[t]; s_bd[t] = make_float2(v, v); }
    if (t < 64) s_aw[t] = aw[t];
    if (t < 4)  s_ab[t] = ab[t];
    __syncthreads();

    int n    = blockIdx.x >> 4;
    int base = (blockIdx.x & 15) * 1024;
    int lane = t & 31, wrp = t >> 5;

    u64t accP = 0ull;   // lane L accumulates reduced value L
    u64t accS = 0ull;   // lane 0 -> asum pair (a0,a1), lane 1 -> (a2,a3)

#pragma unroll 1
    for (int p = 0; p < 4; p++) {
        int pix = base + p * 256 + t;     // 0..16383 within image
        int px = pix & 127;
        int py = pix >> 7;

        // padded coords: input rows 2*py + r (r=0..3); cols xc+1..xc+4
        int xc = 2 * px;

        float xv[16];

        // two sweeps of 8 output channels; channel-outer inside each sweep
#pragma unroll
        for (int sw = 0; sw < 2; sw++) {
            u64t accT[8], accB[8];
#pragma unroll
            for (int o8 = 0; o8 < 8; o8++) {
                accT[o8] = *(const u64t*)&s_bd[sw * 8 + o8];
                accB[o8] = accT[o8];
            }
#pragma unroll
            for (int c = 0; c < 4; c++) {
                u64t prc[4][3];
                const float* cp = g_h1p + (size_t)(n * 4 + c) * H1CH
                                        + (size_t)(2 * py) * H1W + xc;
#pragma unroll
                for (int r = 0; r < 4; r++) {
                    const float* rp = cp + r * H1W;
                    float  v0 = __ldg(rp + 1);
                    float2 m  = __ldg((const float2*)(rp + 2));
                    float  v3 = __ldg(rp + 4);
                    PACK2(prc[r][0], v0, m.x);
                    PACK2(prc[r][1], m.x, m.y);
                    PACK2(prc[r][2], m.y, v3);
                }
#pragma unroll
                for (int o8 = 0; o8 < 8; o8++) {
                    int oc = sw * 8 + o8;
#pragma unroll
                    for (int ky = 0; ky < 3; ky++)
#pragma unroll
                        for (int kx = 0; kx < 3; kx++) {
                            u64t wd = *(const u64t*)&s_wd[((oc * 4 + c) * 3 + ky) * 3 + kx];
                            FMA2(accT[o8], prc[ky    ][kx], wd);
                            FMA2(accB[o8], prc[ky + 1][kx], wd);
                        }
                }
            }
#pragma unroll
            for (int o8 = 0; o8 < 8; o8++) {
                float a00, a01, a10, a11;
                UNPACK2(a00, a01, accT[o8]);
                UNPACK2(a10, a11, accB[o8]);
                xv[sw * 8 + o8] = 0.25f * (fmaxf(a00, 0.f) + fmaxf(a01, 0.f) +
                                           fmaxf(a10, 0.f) + fmaxf(a11, 0.f));
            }
        }

        // NetVLAD soft-assign for this pixel
        float lg[4];
#pragma unroll
        for (int k = 0; k < 4; k++) {
            float s = s_ab[k];
#pragma unroll
            for (int c = 0; c < 16; c++) s = fmaf(xv[c], s_aw[k * 16 + c], s);
            lg[k] = s;
        }
        float mx = fmaxf(fmaxf(lg[0], lg[1]), fmaxf(lg[2], lg[3]));
        float e0 = __expf(lg[0] - mx), e1 = __expf(lg[1] - mx);
        float e2 = __expf(lg[2] - mx), e3 = __expf(lg[3] - mx);
        float inv = 1.0f / (e0 + e1 + e2 + e3);
        float av[4] = {e0 * inv, e1 * inv, e2 * inv, e3 * inv};

        // V[k*8+j] = (a_k*xv[2j], a_k*xv[2j+1])
        u64t xq[8];
#pragma unroll
        for (int j = 0; j < 8; j++) PACK2(xq[j], xv[2 * j], xv[2 * j + 1]);
        u64t V[32];
#pragma unroll
        for (int k = 0; k < 4; k++) {
            u64t ak2; PACK2(ak2, av[k], av[k]);
#pragma unroll
            for (int j = 0; j < 8; j++) MUL2(V[k * 8 + j], ak2, xq[j]);
        }

        // recursive halving: at level o, keep the half selected by (lane&o),
        // send the other; after 5 levels lane l holds warp-sum of value l.
#pragma unroll
        for (int o = 16; o > 0; o >>= 1) {
#pragma unroll
            for (int j = 0; j < o; j++) {
                bool up = (lane & o) != 0;
                u64t give = up ? V[j] : V[j + o];
                u64t got  = __shfl_xor_sync(0xffffffffu, give, o);
                u64t keep = up ? V[j + o] : V[j];
                ADD2(keep, got);
                V[j] = keep;
            }
        }
        ADD2(accP, V[0]);

        // asum pairs: plain allreduce of 2 packed values
        u64t s01, s23;
        PACK2(s01, av[0], av[1]);
        PACK2(s23, av[2], av[3]);
#pragma unroll
        for (int o = 16; o > 0; o >>= 1) {
            u64t q0 = __shfl_xor_sync(0xffffffffu, s01, o); ADD2(s01, q0);
            u64t q1 = __shfl_xor_sync(0xffffffffu, s23, o); ADD2(s23, q1);
        }
        if (lane == 0) ADD2(accS, s01);
        if (lane == 1) ADD2(accS, s23);
    }

    // per-warp partials -> cross-warp sum -> deterministic chunk partial
    s_red[wrp][lane] = accP;
    if (lane < 2) s_red[wrp][32 + lane] = accS;
    __syncthreads();
    if (t < 34) {
        u64t s = s_red[0][t];
#pragma unroll
        for (int wq = 1; wq < 8; wq++) ADD2(s, s_red[wq][t]);
        g_vpart[blockIdx.x * 34 + t] = s;   // blockIdx.x == n*16 + chunk
    }
}

// ---------------------------------------------------------------------------
// Kernel 3: reduce 16 chunk-partials; vlad[k,c] = acc - asum[k]*cent[k,c];
// intra L2 norm over c; global L2 norm; out = vlad @ lin_w.T + lin_b.
// grid: 32 blocks x 64 threads. g_vpart pair j holds floats (2j, 2j+1):
// j<32 -> vlad[2j],vlad[2j+1]; j=32 -> asum0,asum1; j=33 -> asum2,asum3.
// ---------------------------------------------------------------------------
__global__ void __launch_bounds__(64) k_head(
    const float* __restrict__ cent, const float* __restrict__ lw,
    const float* __restrict__ lb, float* __restrict__ out)
{
    __shared__ float s_v[64];
    __shared__ float s_n[4];
    __shared__ float s_g;
    int n = blockIdx.x, t = threadIdx.x;

    const float* p = (const float*)(g_vpart + (size_t)n * 16 * 34);
    float acc = 0.f, asum = 0.f;
    int k = t >> 4;
#pragma unroll
    for (int s = 0; s < 16; s++) {
        acc  += p[s * 68 + t];
        asum += p[s * 68 + 64 + k];
    }
    float v = acc - asum * cent[t];
    s_v[t] = v;
    __syncthreads();

    if (t < 4) {
        float s = 0.f;
#pragma unroll
        for (int c = 0; c < 16; c++) { float q = s_v[t * 16 + c]; s += q * q; }
        s_n[t] = fmaxf(sqrtf(s), 1e-12f);
    }
    __syncthreads();
    v = s_v[t] / s_n[k];
    s_v[t] = v;
    __syncthreads();
    if (t == 0) {
        float s = 0.f;
#pragma unroll
        for (int i = 0; i < 64; i++) s += s_v[i] * s_v[i];
        s_g = fmaxf(sqrtf(s), 1e-12f);
    }
    __syncthreads();
    if (t < 7) {
        float ig = 1.0f / s_g;
        float s = lb[t];
#pragma unroll
        for (int i = 0; i < 64; i++) s = fmaf(s_v[i] * ig, lw[t * 64 + i], s);
        out[n * 7 + t] = s;
    }
}

// ---------------------------------------------------------------------------
extern "C" void kernel_launch(void* const* d_in, const int* in_sizes, int n_in,
                              void* d_out, int out_size)
{
    const float* x     = (const float*)d_in[0];
    const float* c1w   = (const float*)d_in[1];
    const float* c1b   = (const float*)d_in[2];
    const float* c2w   = (const float*)d_in[3];
    const float* c2b   = (const float*)d_in[4];
    const float* cent  = (const float*)d_in[5];
    const float* aw    = (const float*)d_in[6];
    const float* ab    = (const float*)d_in[7];
    const float* lw    = (const float*)d_in[8];
    const float* lb    = (const float*)d_in[9];
    float* out = (float*)d_out;

    k_zero<<<NIMG * 4, 256>>>();
    k_conv1<<<NIMG * 256 * 128 / 256, 256>>>(x, c1w, c1b);
    k_conv2_vlad<<<NIMG * 16384 / 1024, 256>>>(c2w, c2b, aw, ab);
    k_head<<<NIMG, 64>>>(cent, lw, lb, out);
}